// round 15
// baseline (speedup 1.0000x reference)
#include <cuda_runtime.h>
#include <cuda_bf16.h>

// Collapsed forward (linear in context_batch -> batch reduces to 2 scalars):
//   u_i = r_i @ Wv   (r0,r1 = rows of ctx_w, r2 = ctx_b; u2 += bv)
//   w_i = u_i @ Wo   (w2 += bo)
//   P_i[s,h] = w_i @ Whead[s,h]  (+bias)
//   out[h,b,:] = c0[b]*P0 + c1[b]*P1 + P2  (selected by sid[b])
//
// R12: 8 independent clusters x 8 CTAs (no cross-cluster sync ever).
//  - Stage-A Wv loads hoisted into registers at t=0 (overlap cold DRAM
//    with smem setup instead of serializing after it).
//  - Stage C fused into stage B: rank r's head partial only needs the w-cols
//    it just computed (k-slice == d-slice), so no g_w round-trip and no
//    second cluster sync. Chain: A -> sync -> B+C -> sync -> combine.

#define D_MODEL 512
#define NB 16
#define NOUT 64
#define NBLK 64          // 8 clusters x 8 CTAs

__device__ float g_u[8][3][D_MODEL];     // per-cluster u vectors
__device__ float g_ph[8][8][3][NOUT];    // per-cluster per-rank head partials

#define CLUSTER_SYNC_FENCED() do {                                   \
    __syncthreads();                                                 \
    __threadfence();                                                 \
    asm volatile("barrier.cluster.arrive.aligned;" ::: "memory");    \
    asm volatile("barrier.cluster.wait.aligned;"   ::: "memory");    \
    __threadfence();                                                 \
} while (0)

__device__ __forceinline__ void fma4(float4& a, float x, const float4& w) {
    a.x = fmaf(x, w.x, a.x); a.y = fmaf(x, w.y, a.y);
    a.z = fmaf(x, w.z, a.z); a.w = fmaf(x, w.w, a.w);
}

__global__ void __cluster_dims__(8, 1, 1) __launch_bounds__(512, 1)
hivemind_r12(
    const float* __restrict__ cb,      // (16,2)
    const int*   __restrict__ sid,     // (16,)
    const float* __restrict__ ctx_w,   // (2,512)
    const float* __restrict__ ctx_b,   // (512,)
    const float* __restrict__ Wv,      // (512,512)
    const float* __restrict__ bv,      // (512,)
    const float* __restrict__ Wo,      // (512,512)
    const float* __restrict__ bo,      // (512,)
    const float* __restrict__ pred_w,  // (4,512,64)
    const float* __restrict__ pred_b,  // (4,64)
    const float* __restrict__ act_w,   // (4,512,64)
    const float* __restrict__ act_b,   // (4,64)
    float* __restrict__ out)           // [pred(16x64), act(16x64)]
{
    __shared__ float s_x[3][D_MODEL];          // stage input vectors
    __shared__ float s_red[16][3][64];         // per-warp partials
    __shared__ float s_w[3][64];               // this rank's w slice (B->C)
    __shared__ float s_P[3][NOUT];
    __shared__ float s_cb[NB * 2];
    __shared__ int   s_sid[NB];

    const int blk  = blockIdx.x;
    const int t    = threadIdx.x;              // 512 threads
    const int cl   = blk >> 3;                 // cluster 0..7 = (s,h)
    const int r    = blk & 7;                  // rank in cluster
    const int q    = t & 15;                   // col quad (4 cols)
    const int ks   = t >> 4;                   // k-split 0..31
    const int w    = t >> 5;                   // warp 0..15
    const int lane = t & 31;

    const int sp = cl >> 1, h = cl & 1;
    const float* Wh = (h ? act_w : pred_w) + (size_t)sp * D_MODEL * NOUT;
    const float* bh = (h ? act_b : pred_b) + sp * NOUT;
    const int d0 = r * 64 + q * 4;

    // ---- issue ALL stage-A weight loads immediately (cold DRAM overlap) --
    float4 wreg[16];
    #pragma unroll
    for (int i = 0; i < 16; ++i)
        wreg[i] = *(const float4*)&Wv[(size_t)(ks * 16 + i) * D_MODEL + d0];

    // ---- L2 prefetch for stage B (Wo slice) and stage C (Wh slice) ------
    {   // Wo slice: 512 rows x 64 cols = 1024 lines, 2/thread
        #pragma unroll
        for (int j = 0; j < 2; ++j) {
            const int l = t + j * 512;
            const float* p = &Wo[(size_t)(l >> 1) * D_MODEL + r * 64 + (l & 1) * 32];
            asm volatile("prefetch.global.L2 [%0];" :: "l"(p));
        }
        // Wh slice: 64 rows x 64 cols = 128 lines
        if (t < 128) {
            const float* p = &Wh[(size_t)(r * 64 + (t >> 1)) * NOUT + (t & 1) * 32];
            asm volatile("prefetch.global.L2 [%0];" :: "l"(p));
        }
    }

    // ---- smem setup (overlaps the in-flight weight loads) ---------------
    s_x[0][t] = ctx_w[t];
    s_x[1][t] = ctx_w[D_MODEL + t];
    s_x[2][t] = ctx_b[t];
    if (t < NB * 2) s_cb[t]  = cb[t];
    if (t < NB)     s_sid[t] = sid[t];
    __syncthreads();

    // ================= Stage A: u_i = r_i @ Wv ===========================
    {
        float4 a0 = {0,0,0,0}, a1 = {0,0,0,0}, a2 = {0,0,0,0};
        #pragma unroll
        for (int i = 0; i < 16; ++i) {
            const int k = ks * 16 + i;
            fma4(a0, s_x[0][k], wreg[i]);
            fma4(a1, s_x[1][k], wreg[i]);
            fma4(a2, s_x[2][k], wreg[i]);
        }
        a0.x += __shfl_xor_sync(~0u, a0.x, 16); a0.y += __shfl_xor_sync(~0u, a0.y, 16);
        a0.z += __shfl_xor_sync(~0u, a0.z, 16); a0.w += __shfl_xor_sync(~0u, a0.w, 16);
        a1.x += __shfl_xor_sync(~0u, a1.x, 16); a1.y += __shfl_xor_sync(~0u, a1.y, 16);
        a1.z += __shfl_xor_sync(~0u, a1.z, 16); a1.w += __shfl_xor_sync(~0u, a1.w, 16);
        a2.x += __shfl_xor_sync(~0u, a2.x, 16); a2.y += __shfl_xor_sync(~0u, a2.y, 16);
        a2.z += __shfl_xor_sync(~0u, a2.z, 16); a2.w += __shfl_xor_sync(~0u, a2.w, 16);
        if (lane < 16) {
            *(float4*)&s_red[w][0][q * 4] = a0;
            *(float4*)&s_red[w][1][q * 4] = a1;
            *(float4*)&s_red[w][2][q * 4] = a2;
        }
    }
    __syncthreads();
    if (t < 192) {
        const int i = t >> 6, col = t & 63;
        float s = 0.f;
        #pragma unroll
        for (int j = 0; j < 16; ++j) s += s_red[j][i][col];
        if (i == 2) s += bv[r * 64 + col];
        g_u[cl][i][r * 64 + col] = s;
    }
    CLUSTER_SYNC_FENCED();

    // ================= Stage B: w_i = u_i @ Wo (slice stays local) =======
    s_x[0][t] = g_u[cl][0][t];
    s_x[1][t] = g_u[cl][1][t];
    s_x[2][t] = g_u[cl][2][t];
    __syncthreads();
    {
        float4 a0 = {0,0,0,0}, a1 = {0,0,0,0}, a2 = {0,0,0,0};
        #pragma unroll
        for (int i = 0; i < 16; ++i) {
            const int k = ks * 16 + i;
            const float4 wv = *(const float4*)&Wo[(size_t)k * D_MODEL + d0];
            fma4(a0, s_x[0][k], wv);
            fma4(a1, s_x[1][k], wv);
            fma4(a2, s_x[2][k], wv);
        }
        a0.x += __shfl_xor_sync(~0u, a0.x, 16); a0.y += __shfl_xor_sync(~0u, a0.y, 16);
        a0.z += __shfl_xor_sync(~0u, a0.z, 16); a0.w += __shfl_xor_sync(~0u, a0.w, 16);
        a1.x += __shfl_xor_sync(~0u, a1.x, 16); a1.y += __shfl_xor_sync(~0u, a1.y, 16);
        a1.z += __shfl_xor_sync(~0u, a1.z, 16); a1.w += __shfl_xor_sync(~0u, a1.w, 16);
        a2.x += __shfl_xor_sync(~0u, a2.x, 16); a2.y += __shfl_xor_sync(~0u, a2.y, 16);
        a2.z += __shfl_xor_sync(~0u, a2.z, 16); a2.w += __shfl_xor_sync(~0u, a2.w, 16);
        if (lane < 16) {
            *(float4*)&s_red[w][0][q * 4] = a0;
            *(float4*)&s_red[w][1][q * 4] = a1;
            *(float4*)&s_red[w][2][q * 4] = a2;
        }
    }
    __syncthreads();
    if (t < 192) {
        const int i = t >> 6, col = t & 63;
        float s = 0.f;
        #pragma unroll
        for (int j = 0; j < 16; ++j) s += s_red[j][i][col];
        if (i == 2) s += bo[r * 64 + col];
        s_w[i][col] = s;                       // stays in this CTA — no sync!
    }
    __syncthreads();

    // ====== Stage C (fused): head partial over OWN k-slice ===============
    // rank r holds w cols [r*64, r*64+64) == the k rows of Wh it needs.
    {
        const int o0 = q * 4;
        float4 a0 = {0,0,0,0}, a1 = {0,0,0,0}, a2 = {0,0,0,0};
        #pragma unroll
        for (int i = 0; i < 2; ++i) {
            const int kl = ks * 2 + i;                         // local k 0..63
            const float4 wv = *(const float4*)&Wh[(size_t)(r * 64 + kl) * NOUT + o0];
            fma4(a0, s_w[0][kl], wv);
            fma4(a1, s_w[1][kl], wv);
            fma4(a2, s_w[2][kl], wv);
        }
        a0.x += __shfl_xor_sync(~0u, a0.x, 16); a0.y += __shfl_xor_sync(~0u, a0.y, 16);
        a0.z += __shfl_xor_sync(~0u, a0.z, 16); a0.w += __shfl_xor_sync(~0u, a0.w, 16);
        a1.x += __shfl_xor_sync(~0u, a1.x, 16); a1.y += __shfl_xor_sync(~0u, a1.y, 16);
        a1.z += __shfl_xor_sync(~0u, a1.z, 16); a1.w += __shfl_xor_sync(~0u, a1.w, 16);
        a2.x += __shfl_xor_sync(~0u, a2.x, 16); a2.y += __shfl_xor_sync(~0u, a2.y, 16);
        a2.z += __shfl_xor_sync(~0u, a2.z, 16); a2.w += __shfl_xor_sync(~0u, a2.w, 16);
        if (lane < 16) {
            *(float4*)&s_red[w][0][q * 4] = a0;
            *(float4*)&s_red[w][1][q * 4] = a1;
            *(float4*)&s_red[w][2][q * 4] = a2;
        }
    }
    __syncthreads();
    if (t < 192) {
        const int i = t >> 6, o = t & 63;
        float p = 0.f;
        #pragma unroll
        for (int j = 0; j < 16; ++j) p += s_red[j][i][o];
        g_ph[cl][r][i][o] = p;
    }
    CLUSTER_SYNC_FENCED();

    // ---- rank 0: combine 8 rank partials + batch output -----------------
    if (r != 0) return;
    if (t < 192) {
        const int i = t >> 6, o = t & 63;
        float p = 0.f;
        #pragma unroll
        for (int j = 0; j < 8; ++j) p += g_ph[cl][j][i][o];
        if (i == 2) p += bh[o];
        s_P[i][o] = p;
    }
    __syncthreads();
    if (t < NOUT) {
        const float p0 = s_P[0][t], p1 = s_P[1][t], p2 = s_P[2][t];
        #pragma unroll
        for (int b = 0; b < NB; ++b) {
            if (s_sid[b] == sp)
                out[h * NB * NOUT + b * NOUT + t] =
                    fmaf(s_cb[b * 2], p0, fmaf(s_cb[b * 2 + 1], p1, p2));
        }
    }
}

extern "C" void kernel_launch(void* const* d_in, const int* in_sizes, int n_in,
                              void* d_out, int out_size) {
    const float* cb     = (const float*)d_in[1];
    const int*   sid    = (const int*)  d_in[2];
    const float* ctx_w  = (const float*)d_in[16];
    const float* ctx_b  = (const float*)d_in[17];
    const float* ca_wv  = (const float*)d_in[22];
    const float* ca_bv  = (const float*)d_in[23];
    const float* ca_wo  = (const float*)d_in[24];
    const float* ca_bo  = (const float*)d_in[25];
    const float* pred_w = (const float*)d_in[26];
    const float* pred_b = (const float*)d_in[27];
    const float* act_w  = (const float*)d_in[28];
    const float* act_b  = (const float*)d_in[29];
    float* out = (float*)d_out;

    hivemind_r12<<<NBLK, 512>>>(cb, sid, ctx_w, ctx_b,
                                ca_wv, ca_bv, ca_wo, ca_bo,
                                pred_w, pred_b, act_w, act_b, out);
}

// round 16
// speedup vs baseline: 1.2143x; 1.2143x over previous
#include <cuda_runtime.h>
#include <cuda_bf16.h>

// Collapsed forward (linear in context_batch -> batch reduces to 2 scalars):
//   u_i = r_i @ Wv   (r0,r1 = rows of ctx_w, r2 = ctx_b; u2 += bv)
//   w_i = u_i @ Wo   (w2 += bo)
//   P_i[s,h] = w_i @ Whead[s,h]  (+bias)
//   out[h,b,:] = c0[b]*P0 + c1[b]*P1 + P2  (selected by sid[b])
//
// R16: 8 independent clusters x 8 CTAs, ZERO global traffic for intermediates.
//  - u-slice exchange via DSMEM broadcast (st.shared::cluster to all 8 ranks)
//  - head partials pushed via DSMEM into rank 0's smem
//  - Stage C fused after B (k-slice == d-slice, CTA-local)
//  - Wv hoisted to registers at t=0; Wo/Wh L2-prefetched

#define D_MODEL 512
#define NB 16
#define NOUT 64
#define NBLK 64          // 8 clusters x 8 CTAs

#define CLUSTER_SYNC_FENCED() do {                                   \
    __syncthreads();                                                 \
    __threadfence();                                                 \
    asm volatile("barrier.cluster.arrive.aligned;" ::: "memory");    \
    asm volatile("barrier.cluster.wait.aligned;"   ::: "memory");    \
    __threadfence();                                                 \
} while (0)

__device__ __forceinline__ void fma4(float4& a, float x, const float4& w) {
    a.x = fmaf(x, w.x, a.x); a.y = fmaf(x, w.y, a.y);
    a.z = fmaf(x, w.z, a.z); a.w = fmaf(x, w.w, a.w);
}

__device__ __forceinline__ unsigned smem_u32(const void* p) {
    return (unsigned)__cvta_generic_to_shared(p);
}

__device__ __forceinline__ void dsmem_store(unsigned local_addr, int peer, float v) {
    unsigned rem;
    asm volatile("mapa.shared::cluster.u32 %0, %1, %2;"
                 : "=r"(rem) : "r"(local_addr), "r"(peer));
    asm volatile("st.shared::cluster.f32 [%0], %1;" :: "r"(rem), "f"(v) : "memory");
}

__global__ void __cluster_dims__(8, 1, 1) __launch_bounds__(512, 1)
hivemind_r16(
    const float* __restrict__ cb,      // (16,2)
    const int*   __restrict__ sid,     // (16,)
    const float* __restrict__ ctx_w,   // (2,512)
    const float* __restrict__ ctx_b,   // (512,)
    const float* __restrict__ Wv,      // (512,512)
    const float* __restrict__ bv,      // (512,)
    const float* __restrict__ Wo,      // (512,512)
    const float* __restrict__ bo,      // (512,)
    const float* __restrict__ pred_w,  // (4,512,64)
    const float* __restrict__ pred_b,  // (4,64)
    const float* __restrict__ act_w,   // (4,512,64)
    const float* __restrict__ act_b,   // (4,64)
    float* __restrict__ out)           // [pred(16x64), act(16x64)]
{
    __shared__ float s_u[3][D_MODEL];          // full u (DSMEM-assembled)
    __shared__ float s_red[16][3][64];         // per-warp partials
    __shared__ float s_w[3][64];               // this rank's w slice
    __shared__ float s_ph[8][3][NOUT];         // rank0 only: head partials
    __shared__ float s_x[3][D_MODEL];          // stage-A input vectors
    __shared__ float s_cb[NB * 2];
    __shared__ int   s_sid[NB];

    const int blk  = blockIdx.x;
    const int t    = threadIdx.x;              // 512 threads
    const int cl   = blk >> 3;                 // cluster 0..7 = (s,h)
    const int r    = blk & 7;                  // rank in cluster
    const int q    = t & 15;                   // col quad (4 cols)
    const int ks   = t >> 4;                   // k-split 0..31
    const int w    = t >> 5;                   // warp 0..15
    const int lane = t & 31;

    const int sp = cl >> 1, h = cl & 1;
    const float* Wh = (h ? act_w : pred_w) + (size_t)sp * D_MODEL * NOUT;
    const float* bh = (h ? act_b : pred_b) + sp * NOUT;
    const int d0 = r * 64 + q * 4;

    // ---- issue ALL stage-A weight loads immediately (cold-miss overlap) --
    float4 wreg[16];
    #pragma unroll
    for (int i = 0; i < 16; ++i)
        wreg[i] = *(const float4*)&Wv[(size_t)(ks * 16 + i) * D_MODEL + d0];

    // ---- L2 prefetch for stage B (Wo slice) and stage C (Wh slice) ------
    #pragma unroll
    for (int j = 0; j < 2; ++j) {
        const int l = t + j * 512;
        const float* p = &Wo[(size_t)(l >> 1) * D_MODEL + r * 64 + (l & 1) * 32];
        asm volatile("prefetch.global.L2 [%0];" :: "l"(p));
    }
    if (t < 128) {
        const float* p = &Wh[(size_t)(r * 64 + (t >> 1)) * NOUT + (t & 1) * 32];
        asm volatile("prefetch.global.L2 [%0];" :: "l"(p));
    }

    // ---- smem setup (overlaps in-flight weight loads) --------------------
    s_x[0][t] = ctx_w[t];
    s_x[1][t] = ctx_w[D_MODEL + t];
    s_x[2][t] = ctx_b[t];
    if (t < NB * 2) s_cb[t]  = cb[t];
    if (t < NB)     s_sid[t] = sid[t];
    __syncthreads();

    // ================= Stage A: u_i = r_i @ Wv ===========================
    {
        float4 a0 = {0,0,0,0}, a1 = {0,0,0,0}, a2 = {0,0,0,0};
        #pragma unroll
        for (int i = 0; i < 16; ++i) {
            const int k = ks * 16 + i;
            fma4(a0, s_x[0][k], wreg[i]);
            fma4(a1, s_x[1][k], wreg[i]);
            fma4(a2, s_x[2][k], wreg[i]);
        }
        a0.x += __shfl_xor_sync(~0u, a0.x, 16); a0.y += __shfl_xor_sync(~0u, a0.y, 16);
        a0.z += __shfl_xor_sync(~0u, a0.z, 16); a0.w += __shfl_xor_sync(~0u, a0.w, 16);
        a1.x += __shfl_xor_sync(~0u, a1.x, 16); a1.y += __shfl_xor_sync(~0u, a1.y, 16);
        a1.z += __shfl_xor_sync(~0u, a1.z, 16); a1.w += __shfl_xor_sync(~0u, a1.w, 16);
        a2.x += __shfl_xor_sync(~0u, a2.x, 16); a2.y += __shfl_xor_sync(~0u, a2.y, 16);
        a2.z += __shfl_xor_sync(~0u, a2.z, 16); a2.w += __shfl_xor_sync(~0u, a2.w, 16);
        if (lane < 16) {
            *(float4*)&s_red[w][0][q * 4] = a0;
            *(float4*)&s_red[w][1][q * 4] = a1;
            *(float4*)&s_red[w][2][q * 4] = a2;
        }
    }
    __syncthreads();
    // reduce 16 warps -> final u slice, then DSMEM-broadcast to all 8 ranks
    if (t < 192) {
        const int i = t >> 6, col = t & 63;
        float s = 0.f;
        #pragma unroll
        for (int j = 0; j < 16; ++j) s += s_red[j][i][col];
        if (i == 2) s += bv[r * 64 + col];
        const unsigned la = smem_u32(&s_u[i][r * 64 + col]);
        #pragma unroll
        for (int pr = 0; pr < 8; ++pr)
            dsmem_store(la, pr, s);
    }
    CLUSTER_SYNC_FENCED();

    // ================= Stage B: w_i = u_i @ Wo (slice stays local) =======
    {
        float4 a0 = {0,0,0,0}, a1 = {0,0,0,0}, a2 = {0,0,0,0};
        #pragma unroll
        for (int i = 0; i < 16; ++i) {
            const int k = ks * 16 + i;
            const float4 wv = *(const float4*)&Wo[(size_t)k * D_MODEL + d0];
            fma4(a0, s_u[0][k], wv);
            fma4(a1, s_u[1][k], wv);
            fma4(a2, s_u[2][k], wv);
        }
        a0.x += __shfl_xor_sync(~0u, a0.x, 16); a0.y += __shfl_xor_sync(~0u, a0.y, 16);
        a0.z += __shfl_xor_sync(~0u, a0.z, 16); a0.w += __shfl_xor_sync(~0u, a0.w, 16);
        a1.x += __shfl_xor_sync(~0u, a1.x, 16); a1.y += __shfl_xor_sync(~0u, a1.y, 16);
        a1.z += __shfl_xor_sync(~0u, a1.z, 16); a1.w += __shfl_xor_sync(~0u, a1.w, 16);
        a2.x += __shfl_xor_sync(~0u, a2.x, 16); a2.y += __shfl_xor_sync(~0u, a2.y, 16);
        a2.z += __shfl_xor_sync(~0u, a2.z, 16); a2.w += __shfl_xor_sync(~0u, a2.w, 16);
        if (lane < 16) {
            *(float4*)&s_red[w][0][q * 4] = a0;
            *(float4*)&s_red[w][1][q * 4] = a1;
            *(float4*)&s_red[w][2][q * 4] = a2;
        }
    }
    __syncthreads();
    if (t < 192) {
        const int i = t >> 6, col = t & 63;
        float s = 0.f;
        #pragma unroll
        for (int j = 0; j < 16; ++j) s += s_red[j][i][col];
        if (i == 2) s += bo[r * 64 + col];
        s_w[i][col] = s;                       // local only — no sync needed
    }
    __syncthreads();

    // ====== Stage C (fused): head partial over OWN k-slice ===============
    {
        const int o0 = q * 4;
        float4 a0 = {0,0,0,0}, a1 = {0,0,0,0}, a2 = {0,0,0,0};
        #pragma unroll
        for (int i = 0; i < 2; ++i) {
            const int kl = ks * 2 + i;                         // local k 0..63
            const float4 wv = *(const float4*)&Wh[(size_t)(r * 64 + kl) * NOUT + o0];
            fma4(a0, s_w[0][kl], wv);
            fma4(a1, s_w[1][kl], wv);
            fma4(a2, s_w[2][kl], wv);
        }
        a0.x += __shfl_xor_sync(~0u, a0.x, 16); a0.y += __shfl_xor_sync(~0u, a0.y, 16);
        a0.z += __shfl_xor_sync(~0u, a0.z, 16); a0.w += __shfl_xor_sync(~0u, a0.w, 16);
        a1.x += __shfl_xor_sync(~0u, a1.x, 16); a1.y += __shfl_xor_sync(~0u, a1.y, 16);
        a1.z += __shfl_xor_sync(~0u, a1.z, 16); a1.w += __shfl_xor_sync(~0u, a1.w, 16);
        a2.x += __shfl_xor_sync(~0u, a2.x, 16); a2.y += __shfl_xor_sync(~0u, a2.y, 16);
        a2.z += __shfl_xor_sync(~0u, a2.z, 16); a2.w += __shfl_xor_sync(~0u, a2.w, 16);
        if (lane < 16) {
            *(float4*)&s_red[w][0][q * 4] = a0;
            *(float4*)&s_red[w][1][q * 4] = a1;
            *(float4*)&s_red[w][2][q * 4] = a2;
        }
    }
    __syncthreads();
    // reduce and push partials straight into rank 0's s_ph via DSMEM
    if (t < 192) {
        const int i = t >> 6, o = t & 63;
        float p = 0.f;
        #pragma unroll
        for (int j = 0; j < 16; ++j) p += s_red[j][i][o];
        dsmem_store(smem_u32(&s_ph[r][i][o]), 0, p);
    }
    CLUSTER_SYNC_FENCED();

    // ---- rank 0: combine 8 rank partials (local smem) + batch output ----
    if (r != 0) return;
    __shared__ float s_P[3][NOUT];
    if (t < 192) {
        const int i = t >> 6, o = t & 63;
        float p = 0.f;
        #pragma unroll
        for (int j = 0; j < 8; ++j) p += s_ph[j][i][o];
        if (i == 2) p += bh[o];
        s_P[i][o] = p;
    }
    __syncthreads();
    if (t < NOUT) {
        const float p0 = s_P[0][t], p1 = s_P[1][t], p2 = s_P[2][t];
        #pragma unroll
        for (int b = 0; b < NB; ++b) {
            if (s_sid[b] == sp)
                out[h * NB * NOUT + b * NOUT + t] =
                    fmaf(s_cb[b * 2], p0, fmaf(s_cb[b * 2 + 1], p1, p2));
        }
    }
}

extern "C" void kernel_launch(void* const* d_in, const int* in_sizes, int n_in,
                              void* d_out, int out_size) {
    const float* cb     = (const float*)d_in[1];
    const int*   sid    = (const int*)  d_in[2];
    const float* ctx_w  = (const float*)d_in[16];
    const float* ctx_b  = (const float*)d_in[17];
    const float* ca_wv  = (const float*)d_in[22];
    const float* ca_bv  = (const float*)d_in[23];
    const float* ca_wo  = (const float*)d_in[24];
    const float* ca_bo  = (const float*)d_in[25];
    const float* pred_w = (const float*)d_in[26];
    const float* pred_b = (const float*)d_in[27];
    const float* act_w  = (const float*)d_in[28];
    const float* act_b  = (const float*)d_in[29];
    float* out = (float*)d_out;

    hivemind_r16<<<NBLK, 512>>>(cb, sid, ctx_w, ctx_b,
                                ca_wv, ca_bv, ca_wo, ca_bo,
                                pred_w, pred_b, act_w, act_b, out);
}

// round 17
// speedup vs baseline: 1.2216x; 1.0060x over previous
#include <cuda_runtime.h>
#include <cuda_bf16.h>

// Collapsed forward (linear in context_batch -> batch reduces to 2 scalars):
//   u_i = r_i @ Wv   (r0,r1 = rows of ctx_w, r2 = ctx_b; u2 += bv)
//   w_i = u_i @ Wo   (w2 += bo)
//   P_i[s,h] = w_i @ Whead[s,h]  (+bias)
//   out[h,b,:] = c0[b]*P0 + c1[b]*P1 + P2  (selected by sid[b])
//
// R17: 8 independent clusters x 8 CTAs, all intermediates via DSMEM.
//  - NO gpu-scope fences: barrier.cluster arrive/wait release/acquire orders
//    shared::cluster traffic; no __syncthreads inside the cluster sync either.
//  - Wv hoisted to regs at t=0; Wo/Wh slices loaded into regs right after the
//    stage-A FMAs (pinned asm loads) so they fly during reduce+DSMEM+sync.
//  - Stage C fused after B (k-slice == d-slice, CTA-local).

#define D_MODEL 512
#define NB 16
#define NOUT 64
#define NBLK 64          // 8 clusters x 8 CTAs

#define CLUSTER_SYNC() do {                                          \
    asm volatile("barrier.cluster.arrive.aligned;" ::: "memory");    \
    asm volatile("barrier.cluster.wait.aligned;"   ::: "memory");    \
} while (0)

__device__ __forceinline__ void fma4(float4& a, float x, const float4& w) {
    a.x = fmaf(x, w.x, a.x); a.y = fmaf(x, w.y, a.y);
    a.z = fmaf(x, w.z, a.z); a.w = fmaf(x, w.w, a.w);
}

__device__ __forceinline__ float4 ldg4v(const float* p) {
    float4 v;
    asm volatile("ld.global.nc.v4.f32 {%0,%1,%2,%3}, [%4];"
                 : "=f"(v.x), "=f"(v.y), "=f"(v.z), "=f"(v.w) : "l"(p));
    return v;
}

__device__ __forceinline__ unsigned smem_u32(const void* p) {
    return (unsigned)__cvta_generic_to_shared(p);
}

__device__ __forceinline__ void dsmem_store(unsigned local_addr, int peer, float v) {
    unsigned rem;
    asm volatile("mapa.shared::cluster.u32 %0, %1, %2;"
                 : "=r"(rem) : "r"(local_addr), "r"(peer));
    asm volatile("st.shared::cluster.f32 [%0], %1;" :: "r"(rem), "f"(v) : "memory");
}

__global__ void __cluster_dims__(8, 1, 1) __launch_bounds__(512, 1)
hivemind_r17(
    const float* __restrict__ cb,      // (16,2)
    const int*   __restrict__ sid,     // (16,)
    const float* __restrict__ ctx_w,   // (2,512)
    const float* __restrict__ ctx_b,   // (512,)
    const float* __restrict__ Wv,      // (512,512)
    const float* __restrict__ bv,      // (512,)
    const float* __restrict__ Wo,      // (512,512)
    const float* __restrict__ bo,      // (512,)
    const float* __restrict__ pred_w,  // (4,512,64)
    const float* __restrict__ pred_b,  // (4,64)
    const float* __restrict__ act_w,   // (4,512,64)
    const float* __restrict__ act_b,   // (4,64)
    float* __restrict__ out)           // [pred(16x64), act(16x64)]
{
    __shared__ float s_u[3][D_MODEL];          // full u (DSMEM-assembled)
    __shared__ float s_red[16][3][64];         // per-warp partials
    __shared__ float s_w[3][64];               // this rank's w slice
    __shared__ float s_ph[8][3][NOUT];         // rank0: head partials
    __shared__ float s_x[3][D_MODEL];          // stage-A input vectors
    __shared__ float s_P[3][NOUT];
    __shared__ float s_cb[NB * 2];
    __shared__ int   s_sid[NB];

    const int blk  = blockIdx.x;
    const int t    = threadIdx.x;              // 512 threads
    const int cl   = blk >> 3;                 // cluster 0..7 = (s,h)
    const int r    = blk & 7;                  // rank in cluster
    const int q    = t & 15;                   // col quad (4 cols)
    const int ks   = t >> 4;                   // k-split 0..31
    const int w    = t >> 5;                   // warp 0..15
    const int lane = t & 31;

    const int sp = cl >> 1, h = cl & 1;
    const float* Wh = (h ? act_w : pred_w) + (size_t)sp * D_MODEL * NOUT;
    const float* bh = (h ? act_b : pred_b) + sp * NOUT;
    const int d0 = r * 64 + q * 4;

    // ---- issue ALL stage-A weight loads immediately (cold-miss overlap) --
    float4 wreg[16];
    #pragma unroll
    for (int i = 0; i < 16; ++i)
        wreg[i] = *(const float4*)&Wv[(size_t)(ks * 16 + i) * D_MODEL + d0];

    // ---- L2 prefetch for stage B (Wo slice) and stage C (Wh slice) ------
    #pragma unroll
    for (int j = 0; j < 2; ++j) {
        const int l = t + j * 512;
        const float* p = &Wo[(size_t)(l >> 1) * D_MODEL + r * 64 + (l & 1) * 32];
        asm volatile("prefetch.global.L2 [%0];" :: "l"(p));
    }
    if (t < 128) {
        const float* p = &Wh[(size_t)(r * 64 + (t >> 1)) * NOUT + (t & 1) * 32];
        asm volatile("prefetch.global.L2 [%0];" :: "l"(p));
    }

    // ---- smem setup (overlaps in-flight weight loads) --------------------
    s_x[0][t] = ctx_w[t];
    s_x[1][t] = ctx_w[D_MODEL + t];
    s_x[2][t] = ctx_b[t];
    if (t < NB * 2) s_cb[t]  = cb[t];
    if (t < NB)     s_sid[t] = sid[t];
    __syncthreads();

    // ================= Stage A: u_i = r_i @ Wv ===========================
    float4 a0 = {0,0,0,0}, a1 = {0,0,0,0}, a2 = {0,0,0,0};
    #pragma unroll
    for (int i = 0; i < 16; ++i) {
        const int k = ks * 16 + i;
        fma4(a0, s_x[0][k], wreg[i]);
        fma4(a1, s_x[1][k], wreg[i]);
        fma4(a2, s_x[2][k], wreg[i]);
    }

    // ---- early-issue stage B + C weights (regs free; pinned placement) --
    // These loads overlap the reduce + DSMEM broadcast + cluster sync below.
    float4 wb[16];
    #pragma unroll
    for (int i = 0; i < 16; ++i)
        wb[i] = ldg4v(&Wo[(size_t)(ks * 16 + i) * D_MODEL + d0]);
    float4 wc[2];
    #pragma unroll
    for (int i = 0; i < 2; ++i)
        wc[i] = ldg4v(&Wh[(size_t)(r * 64 + ks * 2 + i) * NOUT + q * 4]);

    // ---- stage A reduce + DSMEM broadcast -------------------------------
    a0.x += __shfl_xor_sync(~0u, a0.x, 16); a0.y += __shfl_xor_sync(~0u, a0.y, 16);
    a0.z += __shfl_xor_sync(~0u, a0.z, 16); a0.w += __shfl_xor_sync(~0u, a0.w, 16);
    a1.x += __shfl_xor_sync(~0u, a1.x, 16); a1.y += __shfl_xor_sync(~0u, a1.y, 16);
    a1.z += __shfl_xor_sync(~0u, a1.z, 16); a1.w += __shfl_xor_sync(~0u, a1.w, 16);
    a2.x += __shfl_xor_sync(~0u, a2.x, 16); a2.y += __shfl_xor_sync(~0u, a2.y, 16);
    a2.z += __shfl_xor_sync(~0u, a2.z, 16); a2.w += __shfl_xor_sync(~0u, a2.w, 16);
    if (lane < 16) {
        *(float4*)&s_red[w][0][q * 4] = a0;
        *(float4*)&s_red[w][1][q * 4] = a1;
        *(float4*)&s_red[w][2][q * 4] = a2;
    }
    __syncthreads();
    if (t < 192) {
        const int i = t >> 6, col = t & 63;
        float s = 0.f;
        #pragma unroll
        for (int j = 0; j < 16; ++j) s += s_red[j][i][col];
        if (i == 2) s += bv[r * 64 + col];
        const unsigned la = smem_u32(&s_u[i][r * 64 + col]);
        #pragma unroll
        for (int pr = 0; pr < 8; ++pr)
            dsmem_store(la, pr, s);
    }
    CLUSTER_SYNC();                            // release/acquire: DSMEM ordered

    // ================= Stage B: w_i = u_i @ Wo (from regs) ===============
    a0 = make_float4(0,0,0,0); a1 = make_float4(0,0,0,0); a2 = make_float4(0,0,0,0);
    #pragma unroll
    for (int i = 0; i < 16; ++i) {
        const int k = ks * 16 + i;
        fma4(a0, s_u[0][k], wb[i]);
        fma4(a1, s_u[1][k], wb[i]);
        fma4(a2, s_u[2][k], wb[i]);
    }
    a0.x += __shfl_xor_sync(~0u, a0.x, 16); a0.y += __shfl_xor_sync(~0u, a0.y, 16);
    a0.z += __shfl_xor_sync(~0u, a0.z, 16); a0.w += __shfl_xor_sync(~0u, a0.w, 16);
    a1.x += __shfl_xor_sync(~0u, a1.x, 16); a1.y += __shfl_xor_sync(~0u, a1.y, 16);
    a1.z += __shfl_xor_sync(~0u, a1.z, 16); a1.w += __shfl_xor_sync(~0u, a1.w, 16);
    a2.x += __shfl_xor_sync(~0u, a2.x, 16); a2.y += __shfl_xor_sync(~0u, a2.y, 16);
    a2.z += __shfl_xor_sync(~0u, a2.z, 16); a2.w += __shfl_xor_sync(~0u, a2.w, 16);
    if (lane < 16) {
        *(float4*)&s_red[w][0][q * 4] = a0;
        *(float4*)&s_red[w][1][q * 4] = a1;
        *(float4*)&s_red[w][2][q * 4] = a2;
    }
    __syncthreads();
    if (t < 192) {
        const int i = t >> 6, col = t & 63;
        float s = 0.f;
        #pragma unroll
        for (int j = 0; j < 16; ++j) s += s_red[j][i][col];
        if (i == 2) s += bo[r * 64 + col];
        s_w[i][col] = s;                       // CTA-local — no cluster sync
    }
    __syncthreads();

    // ====== Stage C (fused): head partial over OWN k-slice (from regs) ===
    a0 = make_float4(0,0,0,0); a1 = make_float4(0,0,0,0); a2 = make_float4(0,0,0,0);
    #pragma unroll
    for (int i = 0; i < 2; ++i) {
        const int kl = ks * 2 + i;
        fma4(a0, s_w[0][kl], wc[i]);
        fma4(a1, s_w[1][kl], wc[i]);
        fma4(a2, s_w[2][kl], wc[i]);
    }
    a0.x += __shfl_xor_sync(~0u, a0.x, 16); a0.y += __shfl_xor_sync(~0u, a0.y, 16);
    a0.z += __shfl_xor_sync(~0u, a0.z, 16); a0.w += __shfl_xor_sync(~0u, a0.w, 16);
    a1.x += __shfl_xor_sync(~0u, a1.x, 16); a1.y += __shfl_xor_sync(~0u, a1.y, 16);
    a1.z += __shfl_xor_sync(~0u, a1.z, 16); a1.w += __shfl_xor_sync(~0u, a1.w, 16);
    a2.x += __shfl_xor_sync(~0u, a2.x, 16); a2.y += __shfl_xor_sync(~0u, a2.y, 16);
    a2.z += __shfl_xor_sync(~0u, a2.z, 16); a2.w += __shfl_xor_sync(~0u, a2.w, 16);
    if (lane < 16) {
        *(float4*)&s_red[w][0][q * 4] = a0;
        *(float4*)&s_red[w][1][q * 4] = a1;
        *(float4*)&s_red[w][2][q * 4] = a2;
    }
    __syncthreads();
    if (t < 192) {
        const int i = t >> 6, o = t & 63;
        float p = 0.f;
        #pragma unroll
        for (int j = 0; j < 16; ++j) p += s_red[j][i][o];
        dsmem_store(smem_u32(&s_ph[r][i][o]), 0, p);
    }
    CLUSTER_SYNC();

    // ---- rank 0: combine 8 rank partials (local smem) + batch output ----
    if (r != 0) return;
    if (t < 192) {
        const int i = t >> 6, o = t & 63;
        float p = 0.f;
        #pragma unroll
        for (int j = 0; j < 8; ++j) p += s_ph[j][i][o];
        if (i == 2) p += bh[o];
        s_P[i][o] = p;
    }
    __syncthreads();
    if (t < NOUT) {
        const float p0 = s_P[0][t], p1 = s_P[1][t], p2 = s_P[2][t];
        #pragma unroll
        for (int b = 0; b < NB; ++b) {
            if (s_sid[b] == sp)
                out[h * NB * NOUT + b * NOUT + t] =
                    fmaf(s_cb[b * 2], p0, fmaf(s_cb[b * 2 + 1], p1, p2));
        }
    }
}

extern "C" void kernel_launch(void* const* d_in, const int* in_sizes, int n_in,
                              void* d_out, int out_size) {
    const float* cb     = (const float*)d_in[1];
    const int*   sid    = (const int*)  d_in[2];
    const float* ctx_w  = (const float*)d_in[16];
    const float* ctx_b  = (const float*)d_in[17];
    const float* ca_wv  = (const float*)d_in[22];
    const float* ca_bv  = (const float*)d_in[23];
    const float* ca_wo  = (const float*)d_in[24];
    const float* ca_bo  = (const float*)d_in[25];
    const float* pred_w = (const float*)d_in[26];
    const float* pred_b = (const float*)d_in[27];
    const float* act_w  = (const float*)d_in[28];
    const float* act_b  = (const float*)d_in[29];
    float* out = (float*)d_out;

    hivemind_r17<<<NBLK, 512>>>(cb, sid, ctx_w, ctx_b,
                                ca_wv, ca_bv, ca_wo, ca_bo,
                                pred_w, pred_b, act_w, act_b, out);
}